// round 9
// baseline (speedup 1.0000x reference)
#include <cuda_runtime.h>
#include <cuda_fp16.h>
#include <cuda_fp8.h>
#include <cstdint>

// Problem dims
constexpr int BATCH    = 8192;
constexpr int IN_SIZE  = 4096;
constexpr int HIDDEN   = 4096;
constexpr int OUT_SIZE = 1024;
constexpr int K2_IN  = 2 * IN_SIZE;    // 8192 bytes per act row (hi/lo interleave)
constexpr int K2_HID = 2 * HIDDEN;     // 8192

// GEMM tiling: CTA 256x128, warp tile 64x64, BK2=128 fp8 bytes (=64 real K)
constexpr int TM = 256;
constexpr int TN = 128;
constexpr int BK2 = 128;                        // fp8 bytes per stage-slice
constexpr int STAGES = 3;
constexpr int PITCH = 144;                      // 128B data + 16B pad
constexpr int A_BYTES = TM * PITCH;             // 36864
constexpr int B_BYTES = TN * PITCH;             // 18432
constexpr int STAGE_B = A_BYTES + B_BYTES;      // 55296
constexpr int SMEM_BYTES = STAGES * STAGE_B;    // 165888

// ---------------- static device scratch ----------------
__device__ __align__(16) uint8_t g_w1q[HIDDEN * K2_IN];
__device__ __align__(16) uint8_t g_w2q[HIDDEN * K2_HID];
__device__ __align__(16) uint8_t g_w3q[OUT_SIZE * K2_HID];
__device__ __align__(16) uint8_t g_aq[BATCH * K2_IN];    // act digits (layer1 in / layer2 out)
__device__ __align__(16) uint8_t g_bq[BATCH * K2_HID];   // layer1 out / layer2 in
__device__ float g_part[3 * 2048];
__device__ float g_sum[3];

// ---------------- fp8 helpers ----------------
__device__ __forceinline__ void f32_to_fp8pair(float v, uint8_t& hi, uint8_t& lo) {
    __nv_fp8_storage_t h = __nv_cvt_float_to_fp8(v, __NV_SATFINITE, __NV_E4M3);
    __half_raw hr = __nv_cvt_fp8_to_halfraw(h, __NV_E4M3);
    float rem = v - __half2float(__half(hr));
    __nv_fp8_storage_t l = __nv_cvt_float_to_fp8(rem, __NV_SATFINITE, __NV_E4M3);
    hi = (uint8_t)h; lo = (uint8_t)l;
}

// ---------------- PTX helpers ----------------
__device__ __forceinline__ uint32_t sptr(const void* p) {
    return (uint32_t)__cvta_generic_to_shared(p);
}
__device__ __forceinline__ void cp16(uint32_t dst_smem, const void* src_gmem) {
    asm volatile("cp.async.cg.shared.global [%0], [%1], 16;\n" :: "r"(dst_smem), "l"(src_gmem));
}
__device__ __forceinline__ void ldsm4(uint32_t* r, uint32_t addr) {
    asm volatile("ldmatrix.sync.aligned.m8n8.x4.shared.b16 {%0,%1,%2,%3}, [%4];"
                 : "=r"(r[0]), "=r"(r[1]), "=r"(r[2]), "=r"(r[3]) : "r"(addr));
}
// fp8 e4m3 MMA, f32 accumulate: m16n8k32
__device__ __forceinline__ void mma_fp8(float* d, const uint32_t* a, const uint32_t* b) {
    asm volatile(
        "mma.sync.aligned.m16n8k32.row.col.f32.e4m3.e4m3.f32 "
        "{%0,%1,%2,%3}, {%4,%5,%6,%7}, {%8,%9}, {%0,%1,%2,%3};"
        : "+f"(d[0]), "+f"(d[1]), "+f"(d[2]), "+f"(d[3])
        : "r"(a[0]), "r"(a[1]), "r"(a[2]), "r"(a[3]), "r"(b[0]), "r"(b[1]));
}

// ---------------- prep kernels ----------------
// weights -> duplicated-digit fp8 signs (2 bytes per weight), plus |w| partial sums
__global__ void sign_quant_kernel(const float4* __restrict__ w4,
                                  uint8_t* __restrict__ out, int n4, int layer) {
    float s = 0.f;
    for (int i = blockIdx.x * blockDim.x + threadIdx.x; i < n4; i += gridDim.x * blockDim.x) {
        float4 v = w4[i];
        s += fabsf(v.x) + fabsf(v.y) + fabsf(v.z) + fabsf(v.w);
        // e4m3: +1 = 0x38, -1 = 0xB8, 0 = 0x00; duplicate each into 2 bytes
        uint32_t b0 = (v.x > 0.f) ? 0x38u : ((v.x < 0.f) ? 0xB8u : 0u);
        uint32_t b1 = (v.y > 0.f) ? 0x38u : ((v.y < 0.f) ? 0xB8u : 0u);
        uint32_t b2 = (v.z > 0.f) ? 0x38u : ((v.z < 0.f) ? 0xB8u : 0u);
        uint32_t b3 = (v.w > 0.f) ? 0x38u : ((v.w < 0.f) ? 0xB8u : 0u);
        uint32_t lo32 = b0 | (b0 << 8) | (b1 << 16) | (b1 << 24);
        uint32_t hi32 = b2 | (b2 << 8) | (b3 << 16) | (b3 << 24);
        uint2 p = make_uint2(lo32, hi32);
        *reinterpret_cast<uint2*>(out + (size_t)i * 8) = p;
    }
    __shared__ float red[256];
    red[threadIdx.x] = s;
    __syncthreads();
    for (int o = 128; o > 0; o >>= 1) {
        if (threadIdx.x < o) red[threadIdx.x] += red[threadIdx.x + o];
        __syncthreads();
    }
    if (threadIdx.x == 0) g_part[layer * 2048 + blockIdx.x] = red[0];
}

__global__ void finalize_sum_kernel() {
    __shared__ float red[1024];
    int l = blockIdx.x, t = threadIdx.x;
    red[t] = g_part[l * 2048 + t] + g_part[l * 2048 + 1024 + t];
    __syncthreads();
    for (int o = 512; o > 0; o >>= 1) {
        if (t < o) red[t] += red[t + o];
        __syncthreads();
    }
    if (t == 0) g_sum[l] = red[0];
}

// f32 x -> interleaved (hi,lo) fp8 digits
__global__ void quant_x_kernel(const float4* __restrict__ x4,
                               uint8_t* __restrict__ out, int n4) {
    for (int i = blockIdx.x * blockDim.x + threadIdx.x; i < n4; i += gridDim.x * blockDim.x) {
        float4 v = x4[i];
        uint8_t h0, l0, h1, l1, h2, l2, h3, l3;
        f32_to_fp8pair(v.x, h0, l0);
        f32_to_fp8pair(v.y, h1, l1);
        f32_to_fp8pair(v.z, h2, l2);
        f32_to_fp8pair(v.w, h3, l3);
        uint32_t lo32 = (uint32_t)h0 | ((uint32_t)l0 << 8) | ((uint32_t)h1 << 16) | ((uint32_t)l1 << 24);
        uint32_t hi32 = (uint32_t)h2 | ((uint32_t)l2 << 8) | ((uint32_t)h3 << 16) | ((uint32_t)l3 << 24);
        *reinterpret_cast<uint2*>(out + (size_t)i * 8) = make_uint2(lo32, hi32);
    }
}

// ---------------- fused binarized GEMM (fp8 e4m3 digit-interleaved) ----------------
// Y[M,N] = alpha * (Adig[M,K2] @ Wdig[N,K2]^T) + bias
// EPI0: relu -> fp8 digit pairs ; EPI1: sigmoid -> f32
template <int EPI>
__global__ void __launch_bounds__(256, 1) gemm_fp8(
    const uint8_t* __restrict__ A, const uint8_t* __restrict__ Bs,
    const float* __restrict__ bias, const float* __restrict__ sumAbs, float invCnt,
    int K2, int N,
    uint8_t* __restrict__ oQ, float* __restrict__ oF) {
    extern __shared__ __align__(128) uint8_t smem[];
    const int tid  = threadIdx.x;
    const int lane = tid & 31;
    const int warp = tid >> 5;
    const int wm = warp & 3;   // 4 warp-rows of 64
    const int wn = warp >> 2;  // 2 warp-cols of 64
    const int bm = blockIdx.y, bn = blockIdx.x;
    const int KT = K2 / BK2;   // 64

    const uint8_t* gA = A  + (size_t)bm * TM * K2;
    const uint8_t* gB = Bs + (size_t)bn * TN * K2;

    const int crow = tid >> 3;        // 0..31
    const int ccol = (tid & 7) * 16;  // 16B chunks (128B data/row)

    auto issue = [&](int kt, int stage) {
        uint8_t* sa = smem + stage * STAGE_B;
        uint8_t* sb = sa + A_BYTES;
        const int kof = kt * BK2;
#pragma unroll
        for (int rr = 0; rr < 8; rr++) {
            const int row = rr * 32 + crow;
            cp16(sptr(sa + row * PITCH + ccol), gA + (size_t)row * K2 + kof + ccol);
        }
#pragma unroll
        for (int rr = 0; rr < 4; rr++) {
            const int row = rr * 32 + crow;
            cp16(sptr(sb + row * PITCH + ccol), gB + (size_t)row * K2 + kof + ccol);
        }
    };

    float acc[4][8][4];
#pragma unroll
    for (int i = 0; i < 4; i++)
#pragma unroll
        for (int j = 0; j < 8; j++)
#pragma unroll
            for (int v = 0; v < 4; v++) acc[i][j][v] = 0.f;

    // byte offsets in tile (fragment layout = f16 pattern scaled to bytes)
    const int a_off = (wm * 64 + (lane & 15)) * PITCH + (lane >> 4) * 16;
    const int b_off = (wn * 64 + ((lane >> 4) & 1) * 8 + (lane & 7)) * PITCH
                    + ((lane >> 3) & 1) * 16;

    issue(0, 0);
    asm volatile("cp.async.commit_group;" ::: "memory");
    issue(1, 1);
    asm volatile("cp.async.commit_group;" ::: "memory");

    for (int kt = 0; kt < KT; kt++) {
        const int stage = kt % STAGES;
        asm volatile("cp.async.wait_group 1;" ::: "memory");
        __syncthreads();
        const int kn = kt + 2;
        if (kn < KT) issue(kn, kn % STAGES);
        asm volatile("cp.async.commit_group;" ::: "memory");

        const uint8_t* sA = smem + stage * STAGE_B;
        const uint8_t* sB = sA + A_BYTES;
#pragma unroll
        for (int ks = 0; ks < 4; ks++) {     // 4 x k32 (fp8 bytes) per BK2=128
            const int kc = ks * 32;
            uint32_t af[4][4], bf[8][2];
#pragma unroll
            for (int i = 0; i < 4; i++)
                ldsm4(af[i], sptr(sA + a_off + i * 16 * PITCH + kc));
#pragma unroll
            for (int jj = 0; jj < 4; jj++) {
                uint32_t r[4];
                ldsm4(r, sptr(sB + b_off + jj * 16 * PITCH + kc));
                bf[2 * jj][0] = r[0]; bf[2 * jj][1] = r[1];
                bf[2 * jj + 1][0] = r[2]; bf[2 * jj + 1][1] = r[3];
            }
#pragma unroll
            for (int i = 0; i < 4; i++)
#pragma unroll
                for (int j = 0; j < 8; j++)
                    mma_fp8(acc[i][j], af[i], bf[j]);
        }
    }

    // ---------------- epilogue ----------------
    const float alpha = __ldg(sumAbs) * invCnt;
    const int r0 = bm * TM + wm * 64 + (lane >> 2);
    const int c0 = bn * TN + wn * 64 + (lane & 3) * 2;
    const int K2out = 2 * N;
#pragma unroll
    for (int i = 0; i < 4; i++) {
#pragma unroll
        for (int j = 0; j < 8; j++) {
            int row = r0 + i * 16;
            int col = c0 + j * 8;
            float bx = __ldg(bias + col), by = __ldg(bias + col + 1);
            float v00 = acc[i][j][0] * alpha + bx;
            float v01 = acc[i][j][1] * alpha + by;
            float v10 = acc[i][j][2] * alpha + bx;
            float v11 = acc[i][j][3] * alpha + by;
            if (EPI == 0) {
                v00 = fmaxf(v00, 0.f); v01 = fmaxf(v01, 0.f);
                v10 = fmaxf(v10, 0.f); v11 = fmaxf(v11, 0.f);
                uint8_t h00, l00, h01, l01, h10, l10, h11, l11;
                f32_to_fp8pair(v00, h00, l00);
                f32_to_fp8pair(v01, h01, l01);
                f32_to_fp8pair(v10, h10, l10);
                f32_to_fp8pair(v11, h11, l11);
                uint32_t p0 = (uint32_t)h00 | ((uint32_t)l00 << 8)
                            | ((uint32_t)h01 << 16) | ((uint32_t)l01 << 24);
                uint32_t p1 = (uint32_t)h10 | ((uint32_t)l10 << 8)
                            | ((uint32_t)h11 << 16) | ((uint32_t)l11 << 24);
                *reinterpret_cast<uint32_t*>(oQ + (size_t)row * K2out + 2 * col)       = p0;
                *reinterpret_cast<uint32_t*>(oQ + (size_t)(row + 8) * K2out + 2 * col) = p1;
            } else {
                float2 s0, s1;
                s0.x = 1.f / (1.f + __expf(-v00));
                s0.y = 1.f / (1.f + __expf(-v01));
                s1.x = 1.f / (1.f + __expf(-v10));
                s1.y = 1.f / (1.f + __expf(-v11));
                *reinterpret_cast<float2*>(oF + (size_t)row * N + col)       = s0;
                *reinterpret_cast<float2*>(oF + (size_t)(row + 8) * N + col) = s1;
            }
        }
    }
}

// ---------------- host launch ----------------
extern "C" void kernel_launch(void* const* d_in, const int* in_sizes, int n_in,
                              void* d_out, int out_size) {
    const float* x  = (const float*)d_in[0];
    const float* w1 = (const float*)d_in[1];
    const float* b1 = (const float*)d_in[2];
    const float* w2 = (const float*)d_in[3];
    const float* b2 = (const float*)d_in[4];
    const float* w3 = (const float*)d_in[5];
    const float* b3 = (const float*)d_in[6];

    void *pw1, *pw2, *pw3, *pa, *pb, *psum;
    cudaGetSymbolAddress(&pw1, g_w1q);
    cudaGetSymbolAddress(&pw2, g_w2q);
    cudaGetSymbolAddress(&pw3, g_w3q);
    cudaGetSymbolAddress(&pa, g_aq);
    cudaGetSymbolAddress(&pb, g_bq);
    cudaGetSymbolAddress(&psum, g_sum);
    float* sum = (float*)psum;

    sign_quant_kernel<<<2048, 256>>>((const float4*)w1, (uint8_t*)pw1,
                                     HIDDEN * IN_SIZE / 4, 0);
    sign_quant_kernel<<<2048, 256>>>((const float4*)w2, (uint8_t*)pw2,
                                     HIDDEN * HIDDEN / 4, 1);
    sign_quant_kernel<<<2048, 256>>>((const float4*)w3, (uint8_t*)pw3,
                                     OUT_SIZE * HIDDEN / 4, 2);
    finalize_sum_kernel<<<3, 1024>>>();

    quant_x_kernel<<<2048, 256>>>((const float4*)x, (uint8_t*)pa, BATCH * IN_SIZE / 4);

    cudaFuncSetAttribute(gemm_fp8<0>, cudaFuncAttributeMaxDynamicSharedMemorySize, SMEM_BYTES);
    cudaFuncSetAttribute(gemm_fp8<1>, cudaFuncAttributeMaxDynamicSharedMemorySize, SMEM_BYTES);

    gemm_fp8<0><<<dim3(HIDDEN / TN, BATCH / TM), 256, SMEM_BYTES>>>(
        (const uint8_t*)pa, (const uint8_t*)pw1, b1, sum + 0,
        1.0f / ((float)HIDDEN * (float)IN_SIZE),
        K2_IN, HIDDEN, (uint8_t*)pb, nullptr);

    gemm_fp8<0><<<dim3(HIDDEN / TN, BATCH / TM), 256, SMEM_BYTES>>>(
        (const uint8_t*)pb, (const uint8_t*)pw2, b2, sum + 1,
        1.0f / ((float)HIDDEN * (float)HIDDEN),
        K2_HID, HIDDEN, (uint8_t*)pa, nullptr);

    gemm_fp8<1><<<dim3(OUT_SIZE / TN, BATCH / TM), 256, SMEM_BYTES>>>(
        (const uint8_t*)pa, (const uint8_t*)pw3, b3, sum + 2,
        1.0f / ((float)OUT_SIZE * (float)HIDDEN),
        K2_HID, OUT_SIZE, nullptr, (float*)d_out);
}

// round 10
// speedup vs baseline: 1.9430x; 1.9430x over previous
#include <cuda_runtime.h>
#include <cuda_fp16.h>
#include <cstdint>

using f16 = __half;

// Problem dims
constexpr int BATCH    = 8192;
constexpr int IN_SIZE  = 4096;
constexpr int HIDDEN   = 4096;
constexpr int OUT_SIZE = 1024;

// GEMM tiling: CTA tile 128x128, warp tile 64x32 (2x4 warps), BK=64, 2 CTAs/SM
constexpr int TM = 128;
constexpr int TN = 128;
constexpr int BK = 64;
constexpr int STAGES = 3;
constexpr int ROW_ELEMS  = 72;                    // 64 data + 8 pad f16 (144B pitch)
constexpr int A_ELEMS = TM * ROW_ELEMS;           // 9216
constexpr int B_ELEMS = TN * ROW_ELEMS;           // 9216
constexpr int STAGE_ELEMS = A_ELEMS + B_ELEMS;    // 18432
constexpr int SMEM_BYTES = STAGES * STAGE_ELEMS * 2;  // 110592 B -> 2 CTAs/SM

// ---------------- static device scratch ----------------
__device__ f16 g_w1s[HIDDEN * IN_SIZE];
__device__ f16 g_w2s[HIDDEN * HIDDEN];
__device__ f16 g_w3s[OUT_SIZE * HIDDEN];
__device__ f16 g_a[BATCH * IN_SIZE];
__device__ f16 g_b[BATCH * HIDDEN];
__device__ float g_part[3 * 2048];
__device__ float g_sum[3];

// ---------------- PTX helpers ----------------
__device__ __forceinline__ uint32_t sptr(const void* p) {
    return (uint32_t)__cvta_generic_to_shared(p);
}
__device__ __forceinline__ void cp16(const f16* dst_smem, const f16* src_gmem) {
    uint32_t d = sptr(dst_smem);
    asm volatile("cp.async.cg.shared.global [%0], [%1], 16;\n" :: "r"(d), "l"(src_gmem));
}
__device__ __forceinline__ void ldsm4(uint32_t* r, uint32_t addr) {
    asm volatile("ldmatrix.sync.aligned.m8n8.x4.shared.b16 {%0,%1,%2,%3}, [%4];"
                 : "=r"(r[0]), "=r"(r[1]), "=r"(r[2]), "=r"(r[3]) : "r"(addr));
}
__device__ __forceinline__ void mma_f16(float* d, const uint32_t* a, const uint32_t* b) {
    asm volatile(
        "mma.sync.aligned.m16n8k16.row.col.f32.f16.f16.f32 "
        "{%0,%1,%2,%3}, {%4,%5,%6,%7}, {%8,%9}, {%0,%1,%2,%3};"
        : "+f"(d[0]), "+f"(d[1]), "+f"(d[2]), "+f"(d[3])
        : "r"(a[0]), "r"(a[1]), "r"(a[2]), "r"(a[3]), "r"(b[0]), "r"(b[1]));
}

// ---------------- prep kernels ----------------
__global__ void sign_reduce_kernel(const float4* __restrict__ w4,
                                   __half2* __restrict__ ws2,
                                   int n4, int layer) {
    float s = 0.f;
    for (int i = blockIdx.x * blockDim.x + threadIdx.x; i < n4; i += gridDim.x * blockDim.x) {
        float4 v = w4[i];
        s += fabsf(v.x) + fabsf(v.y) + fabsf(v.z) + fabsf(v.w);
        f16 s0 = __float2half((v.x > 0.f) ? 1.f : ((v.x < 0.f) ? -1.f : 0.f));
        f16 s1 = __float2half((v.y > 0.f) ? 1.f : ((v.y < 0.f) ? -1.f : 0.f));
        f16 s2 = __float2half((v.z > 0.f) ? 1.f : ((v.z < 0.f) ? -1.f : 0.f));
        f16 s3 = __float2half((v.w > 0.f) ? 1.f : ((v.w < 0.f) ? -1.f : 0.f));
        ws2[2 * i]     = __halves2half2(s0, s1);
        ws2[2 * i + 1] = __halves2half2(s2, s3);
    }
    __shared__ float red[256];
    red[threadIdx.x] = s;
    __syncthreads();
    for (int o = 128; o > 0; o >>= 1) {
        if (threadIdx.x < o) red[threadIdx.x] += red[threadIdx.x + o];
        __syncthreads();
    }
    if (threadIdx.x == 0) g_part[layer * 2048 + blockIdx.x] = red[0];
}

__global__ void finalize_sum_kernel() {
    __shared__ float red[1024];
    int l = blockIdx.x, t = threadIdx.x;
    red[t] = g_part[l * 2048 + t] + g_part[l * 2048 + 1024 + t];
    __syncthreads();
    for (int o = 512; o > 0; o >>= 1) {
        if (t < o) red[t] += red[t + o];
        __syncthreads();
    }
    if (t == 0) g_sum[l] = red[0];
}

__global__ void convert_kernel(const float4* __restrict__ x4,
                               __half2* __restrict__ h2, int n4) {
    for (int i = blockIdx.x * blockDim.x + threadIdx.x; i < n4; i += gridDim.x * blockDim.x) {
        float4 v = x4[i];
        h2[2 * i]     = __halves2half2(__float2half(v.x), __float2half(v.y));
        h2[2 * i + 1] = __halves2half2(__float2half(v.z), __float2half(v.w));
    }
}

// ---------------- fused binarized GEMM (128x128 CTA, 64x32 warp tiles, 2 CTAs/SM) ----------------
template <int EPI>
__global__ void __launch_bounds__(256, 2) gemm_bwn(
    const f16* __restrict__ A, const f16* __restrict__ Bs,
    const float* __restrict__ bias, const float* __restrict__ sumAbs, float invCnt,
    int K, int N,
    f16* __restrict__ oH, float* __restrict__ oF) {
    extern __shared__ f16 smem[];
    const int tid  = threadIdx.x;
    const int lane = tid & 31;
    const int warp = tid >> 5;
    const int wm = warp & 1;   // 2 warp-rows of 64
    const int wn = warp >> 1;  // 4 warp-cols of 32
    const int bm = blockIdx.y, bn = blockIdx.x;
    const int KT = K / BK;

    const f16* gA = A  + (size_t)bm * TM * K;
    const f16* gB = Bs + (size_t)bn * TN * K;

    const int crow = tid >> 3;        // 0..31
    const int ccol = (tid & 7) * 8;   // 16B chunks (64 elems/row)

    auto issue = [&](int kt, int stage) {
        f16* sa = smem + stage * STAGE_ELEMS;
        f16* sb = sa + A_ELEMS;
        const int kof = kt * BK;
#pragma unroll
        for (int rr = 0; rr < 4; rr++) {
            const int row = rr * 32 + crow;
            cp16(sa + row * ROW_ELEMS + ccol, gA + (size_t)row * K + kof + ccol);
            cp16(sb + row * ROW_ELEMS + ccol, gB + (size_t)row * K + kof + ccol);
        }
    };

    float acc[4][4][4];
#pragma unroll
    for (int i = 0; i < 4; i++)
#pragma unroll
        for (int j = 0; j < 4; j++)
#pragma unroll
            for (int v = 0; v < 4; v++) acc[i][j][v] = 0.f;

    const int a_off = (wm * 64 + (lane & 15)) * ROW_ELEMS + (lane >> 4) * 8;
    const int b_off = (wn * 32 + ((lane >> 4) & 1) * 8 + (lane & 7)) * ROW_ELEMS
                    + ((lane >> 3) & 1) * 8;

    issue(0, 0);
    asm volatile("cp.async.commit_group;" ::: "memory");
    issue(1, 1);
    asm volatile("cp.async.commit_group;" ::: "memory");

    for (int kt = 0; kt < KT; kt++) {
        const int stage = kt % STAGES;
        asm volatile("cp.async.wait_group 1;" ::: "memory");
        __syncthreads();
        const int kn = kt + 2;
        if (kn < KT) issue(kn, kn % STAGES);
        asm volatile("cp.async.commit_group;" ::: "memory");

        const f16* sA = smem + stage * STAGE_ELEMS;
        const f16* sB = sA + A_ELEMS;
#pragma unroll
        for (int ks = 0; ks < 4; ks++) {
            const int kc = ks * 16;
            uint32_t af[4][4], bf[4][2];
#pragma unroll
            for (int i = 0; i < 4; i++)
                ldsm4(af[i], sptr(sA + a_off + (i & 1) * 16 * ROW_ELEMS
                                     + (i >> 1) * 32 * ROW_ELEMS + kc));
#pragma unroll
            for (int jj = 0; jj < 2; jj++) {
                uint32_t r[4];
                ldsm4(r, sptr(sB + b_off + jj * 16 * ROW_ELEMS + kc));
                bf[2 * jj][0] = r[0]; bf[2 * jj][1] = r[1];
                bf[2 * jj + 1][0] = r[2]; bf[2 * jj + 1][1] = r[3];
            }
#pragma unroll
            for (int i = 0; i < 4; i++)
#pragma unroll
                for (int j = 0; j < 4; j++)
                    mma_f16(acc[i][j], af[i], bf[j]);
        }
    }

    // ---------------- epilogue ----------------
    const float alpha = __ldg(sumAbs) * invCnt;
    const int r0 = bm * TM + wm * 64 + (lane >> 2);
    const int c0 = bn * TN + wn * 32 + (lane & 3) * 2;
#pragma unroll
    for (int i = 0; i < 4; i++) {
#pragma unroll
        for (int j = 0; j < 4; j++) {
            int row = r0 + (i & 1) * 16 + (i >> 1) * 32;
            int col = c0 + j * 8;
            float bx = __ldg(bias + col), by = __ldg(bias + col + 1);
            float v00 = acc[i][j][0] * alpha + bx;
            float v01 = acc[i][j][1] * alpha + by;
            float v10 = acc[i][j][2] * alpha + bx;
            float v11 = acc[i][j][3] * alpha + by;
            if (EPI == 0) {
                v00 = fmaxf(v00, 0.f); v01 = fmaxf(v01, 0.f);
                v10 = fmaxf(v10, 0.f); v11 = fmaxf(v11, 0.f);
                size_t i0 = (size_t)row * N + col;
                size_t i1 = (size_t)(row + 8) * N + col;
                *reinterpret_cast<__half2*>(oH + i0) =
                    __halves2half2(__float2half(v00), __float2half(v01));
                *reinterpret_cast<__half2*>(oH + i1) =
                    __halves2half2(__float2half(v10), __float2half(v11));
            } else {
                float2 s0, s1;
                s0.x = 1.f / (1.f + __expf(-v00));
                s0.y = 1.f / (1.f + __expf(-v01));
                s1.x = 1.f / (1.f + __expf(-v10));
                s1.y = 1.f / (1.f + __expf(-v11));
                *reinterpret_cast<float2*>(oF + (size_t)row * N + col)       = s0;
                *reinterpret_cast<float2*>(oF + (size_t)(row + 8) * N + col) = s1;
            }
        }
    }
}

// ---------------- host launch ----------------
extern "C" void kernel_launch(void* const* d_in, const int* in_sizes, int n_in,
                              void* d_out, int out_size) {
    const float* x  = (const float*)d_in[0];
    const float* w1 = (const float*)d_in[1];
    const float* b1 = (const float*)d_in[2];
    const float* w2 = (const float*)d_in[3];
    const float* b2 = (const float*)d_in[4];
    const float* w3 = (const float*)d_in[5];
    const float* b3 = (const float*)d_in[6];

    void *pw1, *pw2, *pw3, *pa, *pb, *psum;
    cudaGetSymbolAddress(&pw1, g_w1s);
    cudaGetSymbolAddress(&pw2, g_w2s);
    cudaGetSymbolAddress(&pw3, g_w3s);
    cudaGetSymbolAddress(&pa, g_a);
    cudaGetSymbolAddress(&pb, g_b);
    cudaGetSymbolAddress(&psum, g_sum);
    float* sum = (float*)psum;

    sign_reduce_kernel<<<2048, 256>>>((const float4*)w1, (__half2*)pw1,
                                      HIDDEN * IN_SIZE / 4, 0);
    sign_reduce_kernel<<<2048, 256>>>((const float4*)w2, (__half2*)pw2,
                                      HIDDEN * HIDDEN / 4, 1);
    sign_reduce_kernel<<<2048, 256>>>((const float4*)w3, (__half2*)pw3,
                                      OUT_SIZE * HIDDEN / 4, 2);
    finalize_sum_kernel<<<3, 1024>>>();

    convert_kernel<<<2048, 256>>>((const float4*)x, (__half2*)pa, BATCH * IN_SIZE / 4);

    cudaFuncSetAttribute(gemm_bwn<0>, cudaFuncAttributeMaxDynamicSharedMemorySize, SMEM_BYTES);
    cudaFuncSetAttribute(gemm_bwn<1>, cudaFuncAttributeMaxDynamicSharedMemorySize, SMEM_BYTES);

    gemm_bwn<0><<<dim3(HIDDEN / TN, BATCH / TM), 256, SMEM_BYTES>>>(
        (const f16*)pa, (const f16*)pw1, b1, sum + 0,
        1.0f / ((float)HIDDEN * (float)IN_SIZE),
        IN_SIZE, HIDDEN, (f16*)pb, nullptr);

    gemm_bwn<0><<<dim3(HIDDEN / TN, BATCH / TM), 256, SMEM_BYTES>>>(
        (const f16*)pb, (const f16*)pw2, b2, sum + 1,
        1.0f / ((float)HIDDEN * (float)HIDDEN),
        HIDDEN, HIDDEN, (f16*)pa, nullptr);

    gemm_bwn<1><<<dim3(OUT_SIZE / TN, BATCH / TM), 256, SMEM_BYTES>>>(
        (const f16*)pa, (const f16*)pw3, b3, sum + 2,
        1.0f / ((float)OUT_SIZE * (float)HIDDEN),
        HIDDEN, OUT_SIZE, nullptr, (float*)d_out);
}

// round 11
// speedup vs baseline: 1.9629x; 1.0102x over previous
#include <cuda_runtime.h>
#include <cuda_fp16.h>
#include <cstdint>

using f16 = __half;

// Problem dims
constexpr int BATCH    = 8192;
constexpr int IN_SIZE  = 4096;
constexpr int HIDDEN   = 4096;
constexpr int OUT_SIZE = 1024;

// GEMM tiling: CTA tile 128x128, warp tile 64x32 (2x4 warps), BK=64, 2 CTAs/SM
constexpr int TM = 128;
constexpr int TN = 128;
constexpr int BK = 64;
constexpr int STAGES = 3;
constexpr int ROW_ELEMS  = 72;                    // 64 data + 8 pad f16 (144B pitch)
constexpr int A_ELEMS = TM * ROW_ELEMS;           // 9216
constexpr int B_ELEMS = TN * ROW_ELEMS;           // 9216
constexpr int STAGE_ELEMS = A_ELEMS + B_ELEMS;    // 18432
constexpr int SMEM_BYTES = STAGES * STAGE_ELEMS * 2;  // 110592 B -> 2 CTAs/SM

// ---------------- static device scratch ----------------
__device__ f16 g_w1s[HIDDEN * IN_SIZE];
__device__ f16 g_w2s[HIDDEN * HIDDEN];
__device__ f16 g_w3s[OUT_SIZE * HIDDEN];
__device__ f16 g_a[BATCH * IN_SIZE];
__device__ f16 g_b[BATCH * HIDDEN];
__device__ float g_part[3 * 2048];
__device__ float g_sum[3];

// ---------------- PTX helpers ----------------
__device__ __forceinline__ uint32_t sptr(const void* p) {
    return (uint32_t)__cvta_generic_to_shared(p);
}
__device__ __forceinline__ void cp16(const f16* dst_smem, const f16* src_gmem) {
    uint32_t d = sptr(dst_smem);
    asm volatile("cp.async.cg.shared.global [%0], [%1], 16;\n" :: "r"(d), "l"(src_gmem));
}
__device__ __forceinline__ void ldsm4(uint32_t* r, uint32_t addr) {
    asm volatile("ldmatrix.sync.aligned.m8n8.x4.shared.b16 {%0,%1,%2,%3}, [%4];"
                 : "=r"(r[0]), "=r"(r[1]), "=r"(r[2]), "=r"(r[3]) : "r"(addr));
}
__device__ __forceinline__ void mma_f16(float* d, const uint32_t* a, const uint32_t* b) {
    asm volatile(
        "mma.sync.aligned.m16n8k16.row.col.f32.f16.f16.f32 "
        "{%0,%1,%2,%3}, {%4,%5,%6,%7}, {%8,%9}, {%0,%1,%2,%3};"
        : "+f"(d[0]), "+f"(d[1]), "+f"(d[2]), "+f"(d[3])
        : "r"(a[0]), "r"(a[1]), "r"(a[2]), "r"(a[3]), "r"(b[0]), "r"(b[1]));
}

// ---------------- shared quant helper (sign -> f16, block partial |w| sums) ----------------
__device__ __forceinline__ void quant_signs(const float4* __restrict__ w4,
                                            __half2* __restrict__ ws2,
                                            int n4, int layer,
                                            int bid, int nblocks, int tid) {
    float s = 0.f;
    for (int i = bid * 256 + tid; i < n4; i += nblocks * 256) {
        float4 v = w4[i];
        s += fabsf(v.x) + fabsf(v.y) + fabsf(v.z) + fabsf(v.w);
        f16 s0 = __float2half((v.x > 0.f) ? 1.f : ((v.x < 0.f) ? -1.f : 0.f));
        f16 s1 = __float2half((v.y > 0.f) ? 1.f : ((v.y < 0.f) ? -1.f : 0.f));
        f16 s2 = __float2half((v.z > 0.f) ? 1.f : ((v.z < 0.f) ? -1.f : 0.f));
        f16 s3 = __float2half((v.w > 0.f) ? 1.f : ((v.w < 0.f) ? -1.f : 0.f));
        ws2[2 * i]     = __halves2half2(s0, s1);
        ws2[2 * i + 1] = __halves2half2(s2, s3);
    }
    __shared__ float red[256];
    red[tid] = s;
    __syncthreads();
    for (int o = 128; o > 0; o >>= 1) {
        if (tid < o) red[tid] += red[tid + o];
        __syncthreads();
    }
    if (tid == 0) g_part[layer * 2048 + bid] = red[0];
}

// ---------------- prep kernel: sign(w1) + convert(x) fused ----------------
__global__ void prep1_kernel(const float4* __restrict__ w1,
                             __half2* __restrict__ w1s,
                             const float4* __restrict__ x4,
                             __half2* __restrict__ xh, int n4w, int n4x) {
    quant_signs(w1, w1s, n4w, 0, blockIdx.x, gridDim.x, threadIdx.x);
    for (int i = blockIdx.x * blockDim.x + threadIdx.x; i < n4x; i += gridDim.x * blockDim.x) {
        float4 v = x4[i];
        xh[2 * i]     = __halves2half2(__float2half(v.x), __float2half(v.y));
        xh[2 * i + 1] = __halves2half2(__float2half(v.z), __float2half(v.w));
    }
}

// reduce g_part[layer][0..nparts) -> g_sum[layer]
__global__ void finalize_one_kernel(int layer, int nparts) {
    __shared__ float red[1024];
    int t = threadIdx.x;
    float s = 0.f;
    for (int i = t; i < nparts; i += 1024) s += g_part[layer * 2048 + i];
    red[t] = s;
    __syncthreads();
    for (int o = 512; o > 0; o >>= 1) {
        if (t < o) red[t] += red[t + o];
        __syncthreads();
    }
    if (t == 0) g_sum[layer] = red[0];
}

// ---------------- fused binarized GEMM + embedded next-layer weight quant ----------------
// blocks with blockIdx.x < NB do the GEMM; blockIdx.x == NB (when wsrc != null) quantize
// the next layer's weights (overlaps the tensor-bound mainloop of co-resident GEMM CTAs).
template <int EPI>
__global__ void __launch_bounds__(256, 2) gemm_bwn(
    const f16* __restrict__ A, const f16* __restrict__ Bs,
    const float* __restrict__ bias, const float* __restrict__ sumAbs, float invCnt,
    int K, int N, int NB,
    f16* __restrict__ oH, float* __restrict__ oF,
    const float4* __restrict__ wsrc, __half2* __restrict__ wdst, int wn4, int wlayer) {
    extern __shared__ f16 smem[];
    const int tid  = threadIdx.x;

    if (blockIdx.x >= NB) {  // embedded prep path
        quant_signs(wsrc, wdst, wn4, wlayer, blockIdx.y, gridDim.y, tid);
        return;
    }

    const int lane = tid & 31;
    const int warp = tid >> 5;
    const int wm = warp & 1;   // 2 warp-rows of 64
    const int wn = warp >> 1;  // 4 warp-cols of 32
    const int bm = blockIdx.y, bn = blockIdx.x;
    const int KT = K / BK;

    const f16* gA = A  + (size_t)bm * TM * K;
    const f16* gB = Bs + (size_t)bn * TN * K;

    const int crow = tid >> 3;        // 0..31
    const int ccol = (tid & 7) * 8;   // 16B chunks (64 elems/row)

    auto issue = [&](int kt, int stage) {
        f16* sa = smem + stage * STAGE_ELEMS;
        f16* sb = sa + A_ELEMS;
        const int kof = kt * BK;
#pragma unroll
        for (int rr = 0; rr < 4; rr++) {
            const int row = rr * 32 + crow;
            cp16(sa + row * ROW_ELEMS + ccol, gA + (size_t)row * K + kof + ccol);
            cp16(sb + row * ROW_ELEMS + ccol, gB + (size_t)row * K + kof + ccol);
        }
    };

    float acc[4][4][4];
#pragma unroll
    for (int i = 0; i < 4; i++)
#pragma unroll
        for (int j = 0; j < 4; j++)
#pragma unroll
            for (int v = 0; v < 4; v++) acc[i][j][v] = 0.f;

    const int a_off = (wm * 64 + (lane & 15)) * ROW_ELEMS + (lane >> 4) * 8;
    const int b_off = (wn * 32 + ((lane >> 4) & 1) * 8 + (lane & 7)) * ROW_ELEMS
                    + ((lane >> 3) & 1) * 8;

    issue(0, 0);
    asm volatile("cp.async.commit_group;" ::: "memory");
    issue(1, 1);
    asm volatile("cp.async.commit_group;" ::: "memory");

    for (int kt = 0; kt < KT; kt++) {
        const int stage = kt % STAGES;
        asm volatile("cp.async.wait_group 1;" ::: "memory");
        __syncthreads();
        const int kn = kt + 2;
        if (kn < KT) issue(kn, kn % STAGES);
        asm volatile("cp.async.commit_group;" ::: "memory");

        const f16* sA = smem + stage * STAGE_ELEMS;
        const f16* sB = sA + A_ELEMS;
#pragma unroll
        for (int ks = 0; ks < 4; ks++) {
            const int kc = ks * 16;
            uint32_t af[4][4], bf[4][2];
#pragma unroll
            for (int i = 0; i < 4; i++)
                ldsm4(af[i], sptr(sA + a_off + (i & 1) * 16 * ROW_ELEMS
                                     + (i >> 1) * 32 * ROW_ELEMS + kc));
#pragma unroll
            for (int jj = 0; jj < 2; jj++) {
                uint32_t r[4];
                ldsm4(r, sptr(sB + b_off + jj * 16 * ROW_ELEMS + kc));
                bf[2 * jj][0] = r[0]; bf[2 * jj][1] = r[1];
                bf[2 * jj + 1][0] = r[2]; bf[2 * jj + 1][1] = r[3];
            }
#pragma unroll
            for (int i = 0; i < 4; i++)
#pragma unroll
                for (int j = 0; j < 4; j++)
                    mma_f16(acc[i][j], af[i], bf[j]);
        }
    }

    // ---------------- epilogue ----------------
    const float alpha = __ldg(sumAbs) * invCnt;
    const int r0 = bm * TM + wm * 64 + (lane >> 2);
    const int c0 = bn * TN + wn * 32 + (lane & 3) * 2;
#pragma unroll
    for (int i = 0; i < 4; i++) {
#pragma unroll
        for (int j = 0; j < 4; j++) {
            int row = r0 + (i & 1) * 16 + (i >> 1) * 32;
            int col = c0 + j * 8;
            float bx = __ldg(bias + col), by = __ldg(bias + col + 1);
            float v00 = acc[i][j][0] * alpha + bx;
            float v01 = acc[i][j][1] * alpha + by;
            float v10 = acc[i][j][2] * alpha + bx;
            float v11 = acc[i][j][3] * alpha + by;
            if (EPI == 0) {
                v00 = fmaxf(v00, 0.f); v01 = fmaxf(v01, 0.f);
                v10 = fmaxf(v10, 0.f); v11 = fmaxf(v11, 0.f);
                size_t i0 = (size_t)row * N + col;
                size_t i1 = (size_t)(row + 8) * N + col;
                *reinterpret_cast<__half2*>(oH + i0) =
                    __halves2half2(__float2half(v00), __float2half(v01));
                *reinterpret_cast<__half2*>(oH + i1) =
                    __halves2half2(__float2half(v10), __float2half(v11));
            } else {
                float2 s0, s1;
                s0.x = 1.f / (1.f + __expf(-v00));
                s0.y = 1.f / (1.f + __expf(-v01));
                s1.x = 1.f / (1.f + __expf(-v10));
                s1.y = 1.f / (1.f + __expf(-v11));
                *reinterpret_cast<float2*>(oF + (size_t)row * N + col)       = s0;
                *reinterpret_cast<float2*>(oF + (size_t)(row + 8) * N + col) = s1;
            }
        }
    }
}

// ---------------- host launch ----------------
extern "C" void kernel_launch(void* const* d_in, const int* in_sizes, int n_in,
                              void* d_out, int out_size) {
    const float* x  = (const float*)d_in[0];
    const float* w1 = (const float*)d_in[1];
    const float* b1 = (const float*)d_in[2];
    const float* w2 = (const float*)d_in[3];
    const float* b2 = (const float*)d_in[4];
    const float* w3 = (const float*)d_in[5];
    const float* b3 = (const float*)d_in[6];

    void *pw1, *pw2, *pw3, *pa, *pb, *psum;
    cudaGetSymbolAddress(&pw1, g_w1s);
    cudaGetSymbolAddress(&pw2, g_w2s);
    cudaGetSymbolAddress(&pw3, g_w3s);
    cudaGetSymbolAddress(&pa, g_a);
    cudaGetSymbolAddress(&pb, g_b);
    cudaGetSymbolAddress(&psum, g_sum);
    float* sum = (float*)psum;

    cudaFuncSetAttribute(gemm_bwn<0>, cudaFuncAttributeMaxDynamicSharedMemorySize, SMEM_BYTES);
    cudaFuncSetAttribute(gemm_bwn<1>, cudaFuncAttributeMaxDynamicSharedMemorySize, SMEM_BYTES);

    // serial prefix: sign(w1) + convert(x), then finalize sum0
    prep1_kernel<<<2048, 256>>>((const float4*)w1, (__half2*)pw1,
                                (const float4*)x, (__half2*)pa,
                                HIDDEN * IN_SIZE / 4, BATCH * IN_SIZE / 4);
    finalize_one_kernel<<<1, 1024>>>(0, 2048);

    // GEMM1 (+ embedded sign(w2) in extra grid column)
    gemm_bwn<0><<<dim3(HIDDEN / TN + 1, BATCH / TM), 256, SMEM_BYTES>>>(
        (const f16*)pa, (const f16*)pw1, b1, sum + 0,
        1.0f / ((float)HIDDEN * (float)IN_SIZE),
        IN_SIZE, HIDDEN, HIDDEN / TN, (f16*)pb, nullptr,
        (const float4*)w2, (__half2*)pw2, HIDDEN * HIDDEN / 4, 1);
    finalize_one_kernel<<<1, 1024>>>(1, BATCH / TM);

    // GEMM2 (+ embedded sign(w3))
    gemm_bwn<0><<<dim3(HIDDEN / TN + 1, BATCH / TM), 256, SMEM_BYTES>>>(
        (const f16*)pb, (const f16*)pw2, b2, sum + 1,
        1.0f / ((float)HIDDEN * (float)HIDDEN),
        HIDDEN, HIDDEN, HIDDEN / TN, (f16*)pa, nullptr,
        (const float4*)w3, (__half2*)pw3, OUT_SIZE * HIDDEN / 4, 2);
    finalize_one_kernel<<<1, 1024>>>(2, BATCH / TM);

    // GEMM3 (no embedded prep)
    gemm_bwn<1><<<dim3(OUT_SIZE / TN, BATCH / TM), 256, SMEM_BYTES>>>(
        (const f16*)pa, (const f16*)pw3, b3, sum + 2,
        1.0f / ((float)OUT_SIZE * (float)HIDDEN),
        HIDDEN, OUT_SIZE, OUT_SIZE / TN, nullptr, (float*)d_out,
        nullptr, nullptr, 0, 0);
}